// round 2
// baseline (speedup 1.0000x reference)
#include <cuda_runtime.h>
#include <math.h>

// ---------------- problem constants ----------------
#define ND 100000
#define NP 100000
#define EE 800000
#define HID 128

// ---------------- scratch (device globals; no runtime alloc) ----------------
__device__ float g_h_d[ND * HID];
__device__ float g_h_p[NP * HID];
__device__ float g_fs_d[ND * HID];
__device__ float g_fs_p[NP * HID];
__device__ float g_agg_d[ND * HID];
__device__ float g_agg_p[NP * HID];
__device__ float g_el_d[ND * 4];
__device__ float g_er_p[NP * 4];
__device__ float g_el_p[NP * 4];
__device__ float g_er_d[ND * 4];
__device__ int g_deg_p[NP];
__device__ int g_deg_d[ND];
__device__ int g_indptr_p[NP + 1];
__device__ int g_indptr_d[ND + 1];
__device__ int g_cursor_p[NP + 1];
__device__ int g_cursor_d[ND + 1];
__device__ int g_csrc_p[EE];
__device__ int g_csrc_d[EE];

__device__ __forceinline__ float lrelu(float v) { return v > 0.f ? v : 0.2f * v; }

// ---------------- GEMM: [M,128] x [128,128] with fused epilogues ----------------
// Block = 256 threads (8 warps) computes a 64-row panel; warp -> 8 rows;
// lane owns 4 consecutive output columns. W (64KB) + A tile (32KB) in dyn smem.
template <bool RELU, bool HAS_BIAS, bool STORE, bool ATTN>
__global__ void __launch_bounds__(256) gemm128(
    const float* __restrict__ A, const float* __restrict__ W,
    const float* __restrict__ bias, float* __restrict__ out,
    const float* __restrict__ attn, float* __restrict__ evec, int M)
{
    extern __shared__ float smem[];
    float* sW = smem;            // 128*128 floats
    float* sA = smem + 16384;    // 64*128 floats
    const int tid = threadIdx.x;

    float4* sW4 = reinterpret_cast<float4*>(sW);
    const float4* W4 = reinterpret_cast<const float4*>(W);
#pragma unroll
    for (int i = 0; i < 16; i++) sW4[tid + 256 * i] = W4[tid + 256 * i];

    const int row0 = blockIdx.x * 64;
    float4* sA4 = reinterpret_cast<float4*>(sA);
    const float4* A4 = reinterpret_cast<const float4*>(A);
    int nrows = M - row0;
    if (nrows > 64) nrows = 64;
    for (int i = tid; i < nrows * 32; i += 256) sA4[i] = A4[row0 * 32 + i];
    for (int i = nrows * 32 + tid; i < 64 * 32; i += 256)
        sA4[i] = make_float4(0.f, 0.f, 0.f, 0.f);
    __syncthreads();

    const int warp = tid >> 5, lane = tid & 31;
    const int rbase = warp * 8;

    float acc[8][4];
#pragma unroll
    for (int r = 0; r < 8; r++) {
        acc[r][0] = 0.f; acc[r][1] = 0.f; acc[r][2] = 0.f; acc[r][3] = 0.f;
    }

#pragma unroll 4
    for (int k = 0; k < 128; k++) {
        float4 wv = sW4[k * 32 + lane];
#pragma unroll
        for (int r = 0; r < 8; r++) {
            float a = sA[(rbase + r) * 128 + k];
            acc[r][0] = fmaf(a, wv.x, acc[r][0]);
            acc[r][1] = fmaf(a, wv.y, acc[r][1]);
            acc[r][2] = fmaf(a, wv.z, acc[r][2]);
            acc[r][3] = fmaf(a, wv.w, acc[r][3]);
        }
    }

    float4 bv = make_float4(0.f, 0.f, 0.f, 0.f);
    if (HAS_BIAS) bv = reinterpret_cast<const float4*>(bias)[lane];
    float4 av = make_float4(0.f, 0.f, 0.f, 0.f);
    if (ATTN) av = reinterpret_cast<const float4*>(attn)[lane];

#pragma unroll
    for (int r = 0; r < 8; r++) {
        int row = row0 + rbase + r;
        if (row >= M) break;
        if (ATTN) {
            // per-head dot with attn vector: cols [lane*4, lane*4+3] all lie in head lane>>3
            float p = acc[r][0] * av.x + acc[r][1] * av.y + acc[r][2] * av.z + acc[r][3] * av.w;
            p += __shfl_xor_sync(0xffffffffu, p, 1);
            p += __shfl_xor_sync(0xffffffffu, p, 2);
            p += __shfl_xor_sync(0xffffffffu, p, 4);
            if ((lane & 7) == 0) evec[row * 4 + (lane >> 3)] = p;
        }
        if (STORE) {
            float4 o;
            o.x = acc[r][0] + bv.x; o.y = acc[r][1] + bv.y;
            o.z = acc[r][2] + bv.z; o.w = acc[r][3] + bv.w;
            if (RELU) {
                o.x = fmaxf(o.x, 0.f); o.y = fmaxf(o.y, 0.f);
                o.z = fmaxf(o.z, 0.f); o.w = fmaxf(o.w, 0.f);
            }
            reinterpret_cast<float4*>(out)[row * 32 + lane] = o;
        }
    }
}

// ---------------- CSR build ----------------
__global__ void count_kernel(const int* __restrict__ dst, int* __restrict__ deg, int E)
{
    int i = blockIdx.x * blockDim.x + threadIdx.x;
    if (i < E) atomicAdd(&deg[dst[i]], 1);
}

__global__ void scan_kernel(const int* __restrict__ deg, int* __restrict__ indptr,
                            int* __restrict__ cursor, int n)
{
    __shared__ int warp_sums[32];
    __shared__ int s_run;
    const int tid = threadIdx.x, lane = tid & 31, wid = tid >> 5;
    if (tid == 0) s_run = 0;
    __syncthreads();
    for (int base = 0; base < n; base += 1024) {
        int i = base + tid;
        int v = (i < n) ? deg[i] : 0;
        int x = v;
#pragma unroll
        for (int o = 1; o < 32; o <<= 1) {
            int y = __shfl_up_sync(0xffffffffu, x, o);
            if (lane >= o) x += y;
        }
        if (lane == 31) warp_sums[wid] = x;
        __syncthreads();
        if (wid == 0) {
            int s = warp_sums[lane];
#pragma unroll
            for (int o = 1; o < 32; o <<= 1) {
                int y = __shfl_up_sync(0xffffffffu, s, o);
                if (lane >= o) s += y;
            }
            warp_sums[lane] = s;
        }
        __syncthreads();
        int run = s_run;
        int excl = run + x - v + (wid ? warp_sums[wid - 1] : 0);
        if (i < n) { indptr[i] = excl; cursor[i] = excl; }
        int total = warp_sums[31];
        __syncthreads();
        if (tid == 0) s_run = run + total;
        __syncthreads();
    }
    if (threadIdx.x == 0) indptr[n] = s_run;
}

__global__ void scatter_kernel(const int* __restrict__ src, const int* __restrict__ dst,
                               int* __restrict__ cursor, int* __restrict__ csrc, int E)
{
    int i = blockIdx.x * blockDim.x + threadIdx.x;
    if (i < E) {
        int p = atomicAdd(&cursor[dst[i]], 1);
        csrc[p] = src[i];
    }
}

// ---------------- per-dst aggregation: edge softmax + weighted gather ----------------
// One warp per dst node. Lane owns 4 consecutive feature columns (head = lane>>3).
__global__ void __launch_bounds__(256) aggregate_kernel(
    const int* __restrict__ indptr, const int* __restrict__ csrc,
    const float* __restrict__ el, const float* __restrict__ er,
    const float* __restrict__ fs, const float* __restrict__ bias,
    float* __restrict__ out, int n_dst)
{
    int gw = (blockIdx.x * blockDim.x + threadIdx.x) >> 5;
    if (gw >= n_dst) return;
    const int lane = threadIdx.x & 31;
    const int node = gw;
    const int start = indptr[node], end = indptr[node + 1];
    const int h = lane >> 3;

    float4 ern = __ldg(reinterpret_cast<const float4*>(er) + node);
    float er_h = (h == 0) ? ern.x : (h == 1) ? ern.y : (h == 2) ? ern.z : ern.w;

    // pass 1: per-head max over incoming edges
    float4 m4 = make_float4(-INFINITY, -INFINITY, -INFINITY, -INFINITY);
    for (int i = start + lane; i < end; i += 32) {
        int s = csrc[i];
        float4 ev = __ldg(reinterpret_cast<const float4*>(el) + s);
        m4.x = fmaxf(m4.x, lrelu(ev.x + ern.x));
        m4.y = fmaxf(m4.y, lrelu(ev.y + ern.y));
        m4.z = fmaxf(m4.z, lrelu(ev.z + ern.z));
        m4.w = fmaxf(m4.w, lrelu(ev.w + ern.w));
    }
#pragma unroll
    for (int o = 16; o > 0; o >>= 1) {
        m4.x = fmaxf(m4.x, __shfl_xor_sync(0xffffffffu, m4.x, o));
        m4.y = fmaxf(m4.y, __shfl_xor_sync(0xffffffffu, m4.y, o));
        m4.z = fmaxf(m4.z, __shfl_xor_sync(0xffffffffu, m4.z, o));
        m4.w = fmaxf(m4.w, __shfl_xor_sync(0xffffffffu, m4.w, o));
    }
    float m_h = (h == 0) ? m4.x : (h == 1) ? m4.y : (h == 2) ? m4.z : m4.w;

    // pass 2: weighted accumulate of fs[src]
    float sum_w = 0.f;
    float4 acc = make_float4(0.f, 0.f, 0.f, 0.f);
    const float4* fs4 = reinterpret_cast<const float4*>(fs);
    for (int i = start; i < end; i++) {
        int s = csrc[i];
        float elh = __ldg(el + s * 4 + h);
        float w = __expf(lrelu(elh + er_h) - m_h);
        sum_w += w;
        float4 f = fs4[s * 32 + lane];
        acc.x = fmaf(w, f.x, acc.x);
        acc.y = fmaf(w, f.y, acc.y);
        acc.z = fmaf(w, f.z, acc.z);
        acc.w = fmaf(w, f.w, acc.w);
    }
    float inv = (end > start) ? (1.0f / sum_w) : 0.f;
    float4 b = reinterpret_cast<const float4*>(bias)[lane];
    float4 o;
    o.x = fmaf(acc.x, inv, b.x);
    o.y = fmaf(acc.y, inv, b.y);
    o.z = fmaf(acc.z, inv, b.z);
    o.w = fmaf(acc.w, inv, b.w);
    reinterpret_cast<float4*>(out)[node * 32 + lane] = o;
}

// ---------------- launch ----------------
extern "C" void kernel_launch(void* const* d_in, const int* in_sizes, int n_in,
                              void* d_out, int out_size)
{
    const float* x_drug  = (const float*)d_in[0];
    const float* x_prot  = (const float*)d_in[1];
    const int*   src_dp  = (const int*)d_in[2];
    const int*   dst_dp  = (const int*)d_in[3];
    const int*   src_pd  = (const int*)d_in[4];
    const int*   dst_pd  = (const int*)d_in[5];
    const float* W_in_d  = (const float*)d_in[6];
    const float* b_in_d  = (const float*)d_in[7];
    const float* W_in_p  = (const float*)d_in[8];
    const float* b_in_p  = (const float*)d_in[9];
    const float* W_dp    = (const float*)d_in[10];
    const float* al_dp   = (const float*)d_in[11];
    const float* ar_dp   = (const float*)d_in[12];
    const float* bias_dp = (const float*)d_in[13];
    const float* W_pd    = (const float*)d_in[14];
    const float* al_pd   = (const float*)d_in[15];
    const float* ar_pd   = (const float*)d_in[16];
    const float* bias_pd = (const float*)d_in[17];
    const float* W_out_d = (const float*)d_in[18];
    const float* b_out_d = (const float*)d_in[19];
    const float* W_out_p = (const float*)d_in[20];
    const float* b_out_p = (const float*)d_in[21];
    float* out = (float*)d_out;

    const int n_drug = in_sizes[0] / HID;
    const int n_prot = in_sizes[1] / HID;
    const int E = in_sizes[2];

    float *h_d, *h_p, *fs_d, *fs_p, *agg_d, *agg_p, *el_d, *er_p, *el_p, *er_d;
    int *deg_p, *deg_d, *indptr_p, *indptr_d, *cursor_p, *cursor_d, *csrc_p, *csrc_d;
    cudaGetSymbolAddress((void**)&h_d, g_h_d);
    cudaGetSymbolAddress((void**)&h_p, g_h_p);
    cudaGetSymbolAddress((void**)&fs_d, g_fs_d);
    cudaGetSymbolAddress((void**)&fs_p, g_fs_p);
    cudaGetSymbolAddress((void**)&agg_d, g_agg_d);
    cudaGetSymbolAddress((void**)&agg_p, g_agg_p);
    cudaGetSymbolAddress((void**)&el_d, g_el_d);
    cudaGetSymbolAddress((void**)&er_p, g_er_p);
    cudaGetSymbolAddress((void**)&el_p, g_el_p);
    cudaGetSymbolAddress((void**)&er_d, g_er_d);
    cudaGetSymbolAddress((void**)&deg_p, g_deg_p);
    cudaGetSymbolAddress((void**)&deg_d, g_deg_d);
    cudaGetSymbolAddress((void**)&indptr_p, g_indptr_p);
    cudaGetSymbolAddress((void**)&indptr_d, g_indptr_d);
    cudaGetSymbolAddress((void**)&cursor_p, g_cursor_p);
    cudaGetSymbolAddress((void**)&cursor_d, g_cursor_d);
    cudaGetSymbolAddress((void**)&csrc_p, g_csrc_p);
    cudaGetSymbolAddress((void**)&csrc_d, g_csrc_d);

    const int SMEM = (16384 + 8192) * (int)sizeof(float);  // 96 KB
    cudaFuncSetAttribute(gemm128<true,  true,  true,  false>, cudaFuncAttributeMaxDynamicSharedMemorySize, SMEM);
    cudaFuncSetAttribute(gemm128<false, false, true,  true >, cudaFuncAttributeMaxDynamicSharedMemorySize, SMEM);
    cudaFuncSetAttribute(gemm128<false, false, false, true >, cudaFuncAttributeMaxDynamicSharedMemorySize, SMEM);
    cudaFuncSetAttribute(gemm128<false, true,  true,  false>, cudaFuncAttributeMaxDynamicSharedMemorySize, SMEM);

    const int gd = (n_drug + 63) / 64;
    const int gp = (n_prot + 63) / 64;
    const int ge = (E + 255) / 256;

    // CSR build (independent of GEMMs)
    cudaMemsetAsync(deg_p, 0, n_prot * sizeof(int));
    cudaMemsetAsync(deg_d, 0, n_drug * sizeof(int));
    count_kernel<<<ge, 256>>>(dst_dp, deg_p, E);
    count_kernel<<<ge, 256>>>(dst_pd, deg_d, E);
    scan_kernel<<<1, 1024>>>(deg_p, indptr_p, cursor_p, n_prot);
    scan_kernel<<<1, 1024>>>(deg_d, indptr_d, cursor_d, n_drug);
    scatter_kernel<<<ge, 256>>>(src_dp, dst_dp, cursor_p, csrc_p, E);
    scatter_kernel<<<ge, 256>>>(src_pd, dst_pd, cursor_d, csrc_d, E);

    // input projections (+relu)
    gemm128<true, true, true, false><<<gd, 256, SMEM>>>(x_drug, W_in_d, b_in_d, h_d, nullptr, nullptr, n_drug);
    gemm128<true, true, true, false><<<gp, 256, SMEM>>>(x_prot, W_in_p, b_in_p, h_p, nullptr, nullptr, n_prot);

    // GAT projections: fs (+el) stored; fd never materialized (only er)
    gemm128<false, false, true,  true><<<gd, 256, SMEM>>>(h_d, W_dp, nullptr, fs_d, al_dp, el_d, n_drug);
    gemm128<false, false, false, true><<<gp, 256, SMEM>>>(h_p, W_dp, nullptr, nullptr, ar_dp, er_p, n_prot);
    gemm128<false, false, true,  true><<<gp, 256, SMEM>>>(h_p, W_pd, nullptr, fs_p, al_pd, el_p, n_prot);
    gemm128<false, false, false, true><<<gd, 256, SMEM>>>(h_d, W_pd, nullptr, nullptr, ar_pd, er_d, n_drug);

    // edge softmax + aggregation (one warp per dst node)
    aggregate_kernel<<<(n_prot * 32 + 255) / 256, 256>>>(indptr_p, csrc_p, el_d, er_p, fs_d, bias_dp, agg_p, n_prot);
    aggregate_kernel<<<(n_drug * 32 + 255) / 256, 256>>>(indptr_d, csrc_d, el_p, er_d, fs_p, bias_pd, agg_d, n_drug);

    // output projections -> d_out (out_drug first, then out_prot)
    gemm128<false, true, true, false><<<gd, 256, SMEM>>>(agg_d, W_out_d, b_out_d, out, nullptr, nullptr, n_drug);
    gemm128<false, true, true, false><<<gp, 256, SMEM>>>(agg_p, W_out_p, b_out_p, out + (size_t)n_drug * HID, nullptr, nullptr, n_prot);
}

// round 3
// speedup vs baseline: 1.3516x; 1.3516x over previous
#include <cuda_runtime.h>
#include <math.h>

// ---------------- problem constants ----------------
#define ND 100000
#define NP 100000
#define EE 800000
#define HID 128

// ---------------- scratch (device globals; no runtime alloc) ----------------
__device__ float g_h_d[ND * HID];
__device__ float g_h_p[NP * HID];
__device__ float g_fs_d[ND * HID];
__device__ float g_fs_p[NP * HID];
__device__ float g_agg_d[ND * HID];
__device__ float g_agg_p[NP * HID];
__device__ float g_el_d[ND * 4];
__device__ float g_er_p[NP * 4];
__device__ float g_el_p[NP * 4];
__device__ float g_er_d[ND * 4];
__device__ float g_Ut_dp[4 * HID];   // folded W_dp @ ar_dp  -> [H,128] (k-major per head)
__device__ float g_Ut_pd[4 * HID];
__device__ int g_deg_p[NP];
__device__ int g_deg_d[ND];
__device__ int g_indptr_p[NP + 1];
__device__ int g_indptr_d[ND + 1];
__device__ int g_cursor_p[NP + 1];
__device__ int g_cursor_d[ND + 1];
__device__ int g_csrc_p[EE];
__device__ int g_csrc_d[EE];
__device__ int g_part_p[1024];
__device__ int g_part_d[1024];

__device__ __forceinline__ float lrelu(float v) { return v > 0.f ? v : 0.2f * v; }

// ---------------- GEMM: [M,128] x [128,128] with fused epilogues ----------------
template <bool RELU, bool HAS_BIAS, bool ATTN>
__global__ void __launch_bounds__(256) gemm128(
    const float* __restrict__ A, const float* __restrict__ W,
    const float* __restrict__ bias, float* __restrict__ out,
    const float* __restrict__ attn, float* __restrict__ evec, int M)
{
    extern __shared__ float smem[];
    float* sW = smem;            // 128*128 floats
    float* sA = smem + 16384;    // 64*128 floats
    const int tid = threadIdx.x;

    float4* sW4 = reinterpret_cast<float4*>(sW);
    const float4* W4 = reinterpret_cast<const float4*>(W);
#pragma unroll
    for (int i = 0; i < 16; i++) sW4[tid + 256 * i] = W4[tid + 256 * i];

    const int row0 = blockIdx.x * 64;
    float4* sA4 = reinterpret_cast<float4*>(sA);
    const float4* A4 = reinterpret_cast<const float4*>(A);
    int nrows = M - row0;
    if (nrows > 64) nrows = 64;
    for (int i = tid; i < nrows * 32; i += 256) sA4[i] = A4[row0 * 32 + i];
    for (int i = nrows * 32 + tid; i < 64 * 32; i += 256)
        sA4[i] = make_float4(0.f, 0.f, 0.f, 0.f);
    __syncthreads();

    const int warp = tid >> 5, lane = tid & 31;
    const int rbase = warp * 8;

    float acc[8][4];
#pragma unroll
    for (int r = 0; r < 8; r++) {
        acc[r][0] = 0.f; acc[r][1] = 0.f; acc[r][2] = 0.f; acc[r][3] = 0.f;
    }

#pragma unroll 4
    for (int k = 0; k < 128; k++) {
        float4 wv = sW4[k * 32 + lane];
#pragma unroll
        for (int r = 0; r < 8; r++) {
            float a = sA[(rbase + r) * 128 + k];
            acc[r][0] = fmaf(a, wv.x, acc[r][0]);
            acc[r][1] = fmaf(a, wv.y, acc[r][1]);
            acc[r][2] = fmaf(a, wv.z, acc[r][2]);
            acc[r][3] = fmaf(a, wv.w, acc[r][3]);
        }
    }

    float4 bv = make_float4(0.f, 0.f, 0.f, 0.f);
    if (HAS_BIAS) bv = reinterpret_cast<const float4*>(bias)[lane];
    float4 av = make_float4(0.f, 0.f, 0.f, 0.f);
    if (ATTN) av = reinterpret_cast<const float4*>(attn)[lane];

#pragma unroll
    for (int r = 0; r < 8; r++) {
        int row = row0 + rbase + r;
        if (row >= M) break;
        if (ATTN) {
            float p = acc[r][0] * av.x + acc[r][1] * av.y + acc[r][2] * av.z + acc[r][3] * av.w;
            p += __shfl_xor_sync(0xffffffffu, p, 1);
            p += __shfl_xor_sync(0xffffffffu, p, 2);
            p += __shfl_xor_sync(0xffffffffu, p, 4);
            if ((lane & 7) == 0) evec[row * 4 + (lane >> 3)] = p;
        }
        float4 o;
        o.x = acc[r][0] + bv.x; o.y = acc[r][1] + bv.y;
        o.z = acc[r][2] + bv.z; o.w = acc[r][3] + bv.w;
        if (RELU) {
            o.x = fmaxf(o.x, 0.f); o.y = fmaxf(o.y, 0.f);
            o.z = fmaxf(o.z, 0.f); o.w = fmaxf(o.w, 0.f);
        }
        reinterpret_cast<float4*>(out)[row * 32 + lane] = o;
    }
}

// ---------------- fold W @ ar -> Ut [H=4][128] ----------------
__global__ void fold_attn_kernel(const float* __restrict__ W,
                                 const float* __restrict__ ar,
                                 float* __restrict__ Ut)
{
    int k = threadIdx.x;  // 0..127
#pragma unroll
    for (int h = 0; h < 4; h++) {
        float s = 0.f;
#pragma unroll
        for (int d = 0; d < 32; d++)
            s += W[k * 128 + h * 32 + d] * ar[h * 32 + d];
        Ut[h * 128 + k] = s;
    }
}

// ---------------- er = h @ Ut (warp per node) ----------------
__global__ void __launch_bounds__(256) er_kernel(
    const float* __restrict__ hfeat, const float* __restrict__ Ut,
    float* __restrict__ er, int n)
{
    int gw = (blockIdx.x * blockDim.x + threadIdx.x) >> 5;
    if (gw >= n) return;
    const int lane = threadIdx.x & 31;
    float4 f = reinterpret_cast<const float4*>(hfeat)[gw * 32 + lane];
    const float4* Ut4 = reinterpret_cast<const float4*>(Ut);
    float p[4];
#pragma unroll
    for (int h = 0; h < 4; h++) {
        float4 u = __ldg(Ut4 + h * 32 + lane);
        p[h] = f.x * u.x + f.y * u.y + f.z * u.z + f.w * u.w;
    }
#pragma unroll
    for (int o = 16; o > 0; o >>= 1) {
#pragma unroll
        for (int h = 0; h < 4; h++)
            p[h] += __shfl_xor_sync(0xffffffffu, p[h], o);
    }
    if (lane == 0)
        reinterpret_cast<float4*>(er)[gw] = make_float4(p[0], p[1], p[2], p[3]);
}

// ---------------- CSR build ----------------
__global__ void count_kernel(const int* __restrict__ dst, int* __restrict__ deg, int E)
{
    int i = blockIdx.x * blockDim.x + threadIdx.x;
    if (i < E) atomicAdd(&deg[dst[i]], 1);
}

// phase A: per-block (1024 elems) sums
__global__ void __launch_bounds__(1024) scan_partA(const int* __restrict__ deg,
                                                   int* __restrict__ part, int n)
{
    __shared__ int ws[32];
    const int tid = threadIdx.x, lane = tid & 31, wid = tid >> 5;
    int i = blockIdx.x * 1024 + tid;
    int v = (i < n) ? deg[i] : 0;
    int s = v;
#pragma unroll
    for (int o = 16; o > 0; o >>= 1) s += __shfl_xor_sync(0xffffffffu, s, o);
    if (lane == 0) ws[wid] = s;
    __syncthreads();
    if (wid == 0) {
        int t = ws[lane];
#pragma unroll
        for (int o = 16; o > 0; o >>= 1) t += __shfl_xor_sync(0xffffffffu, t, o);
        if (lane == 0) part[blockIdx.x] = t;
    }
}

// phase B: exclusive scan of up-to-1024 partials (single block); writes total to indptr[n]
__global__ void __launch_bounds__(1024) scan_partB(int* __restrict__ part,
                                                   int* __restrict__ indptr,
                                                   int nb, int n)
{
    __shared__ int ws[32];
    const int tid = threadIdx.x, lane = tid & 31, wid = tid >> 5;
    int v = (tid < nb) ? part[tid] : 0;
    int x = v;
#pragma unroll
    for (int o = 1; o < 32; o <<= 1) {
        int y = __shfl_up_sync(0xffffffffu, x, o);
        if (lane >= o) x += y;
    }
    if (lane == 31) ws[wid] = x;
    __syncthreads();
    if (wid == 0) {
        int s = ws[lane];
#pragma unroll
        for (int o = 1; o < 32; o <<= 1) {
            int y = __shfl_up_sync(0xffffffffu, s, o);
            if (lane >= o) s += y;
        }
        ws[lane] = s;
    }
    __syncthreads();
    int excl = x - v + (wid ? ws[wid - 1] : 0);
    if (tid < nb) part[tid] = excl;
    if (tid == 1023) indptr[n] = excl + v;  // only valid when nb<=1024 and wid covers; use total below
    if (tid == 0) {
        // robust total write (nb may be < 1024): ws[31] holds full inclusive sum
    }
    __syncthreads();
    if (tid == 0) indptr[n] = ws[31];
}

// phase C: per-block exclusive scan + global offset; writes indptr & cursor
__global__ void __launch_bounds__(1024) scan_partC(const int* __restrict__ deg,
                                                   const int* __restrict__ part,
                                                   int* __restrict__ indptr,
                                                   int* __restrict__ cursor, int n)
{
    __shared__ int ws[32];
    const int tid = threadIdx.x, lane = tid & 31, wid = tid >> 5;
    int i = blockIdx.x * 1024 + tid;
    int v = (i < n) ? deg[i] : 0;
    int x = v;
#pragma unroll
    for (int o = 1; o < 32; o <<= 1) {
        int y = __shfl_up_sync(0xffffffffu, x, o);
        if (lane >= o) x += y;
    }
    if (lane == 31) ws[wid] = x;
    __syncthreads();
    if (wid == 0) {
        int s = ws[lane];
#pragma unroll
        for (int o = 1; o < 32; o <<= 1) {
            int y = __shfl_up_sync(0xffffffffu, s, o);
            if (lane >= o) s += y;
        }
        ws[lane] = s;
    }
    __syncthreads();
    int excl = part[blockIdx.x] + x - v + (wid ? ws[wid - 1] : 0);
    if (i < n) { indptr[i] = excl; cursor[i] = excl; }
}

__global__ void scatter_kernel(const int* __restrict__ src, const int* __restrict__ dst,
                               int* __restrict__ cursor, int* __restrict__ csrc, int E)
{
    int i = blockIdx.x * blockDim.x + threadIdx.x;
    if (i < E) {
        int p = atomicAdd(&cursor[dst[i]], 1);
        csrc[p] = src[i];
    }
}

// ---------------- per-dst aggregation: edge softmax + weighted gather ----------------
__global__ void __launch_bounds__(256) aggregate_kernel(
    const int* __restrict__ indptr, const int* __restrict__ csrc,
    const float* __restrict__ el, const float* __restrict__ er,
    const float* __restrict__ fs, const float* __restrict__ bias,
    float* __restrict__ out, int n_dst)
{
    int gw = (blockIdx.x * blockDim.x + threadIdx.x) >> 5;
    if (gw >= n_dst) return;
    const int lane = threadIdx.x & 31;
    const int node = gw;
    const int start = indptr[node], end = indptr[node + 1];
    const int h = lane >> 3;

    float4 ern = __ldg(reinterpret_cast<const float4*>(er) + node);
    float er_h = (h == 0) ? ern.x : (h == 1) ? ern.y : (h == 2) ? ern.z : ern.w;

    // pass 1: per-head max over incoming edges
    float4 m4 = make_float4(-INFINITY, -INFINITY, -INFINITY, -INFINITY);
    for (int i = start + lane; i < end; i += 32) {
        int s = csrc[i];
        float4 ev = __ldg(reinterpret_cast<const float4*>(el) + s);
        m4.x = fmaxf(m4.x, lrelu(ev.x + ern.x));
        m4.y = fmaxf(m4.y, lrelu(ev.y + ern.y));
        m4.z = fmaxf(m4.z, lrelu(ev.z + ern.z));
        m4.w = fmaxf(m4.w, lrelu(ev.w + ern.w));
    }
#pragma unroll
    for (int o = 16; o > 0; o >>= 1) {
        m4.x = fmaxf(m4.x, __shfl_xor_sync(0xffffffffu, m4.x, o));
        m4.y = fmaxf(m4.y, __shfl_xor_sync(0xffffffffu, m4.y, o));
        m4.z = fmaxf(m4.z, __shfl_xor_sync(0xffffffffu, m4.z, o));
        m4.w = fmaxf(m4.w, __shfl_xor_sync(0xffffffffu, m4.w, o));
    }
    float m_h = (h == 0) ? m4.x : (h == 1) ? m4.y : (h == 2) ? m4.z : m4.w;

    // pass 2: weighted accumulate of fs[src]
    float sum_w = 0.f;
    float4 acc = make_float4(0.f, 0.f, 0.f, 0.f);
    const float4* fs4 = reinterpret_cast<const float4*>(fs);
    for (int i = start; i < end; i++) {
        int s = csrc[i];
        float elh = __ldg(el + s * 4 + h);
        float w = __expf(lrelu(elh + er_h) - m_h);
        sum_w += w;
        float4 f = fs4[s * 32 + lane];
        acc.x = fmaf(w, f.x, acc.x);
        acc.y = fmaf(w, f.y, acc.y);
        acc.z = fmaf(w, f.z, acc.z);
        acc.w = fmaf(w, f.w, acc.w);
    }
    float inv = (end > start) ? (1.0f / sum_w) : 0.f;
    float4 b = reinterpret_cast<const float4*>(bias)[lane];
    float4 o;
    o.x = fmaf(acc.x, inv, b.x);
    o.y = fmaf(acc.y, inv, b.y);
    o.z = fmaf(acc.z, inv, b.z);
    o.w = fmaf(acc.w, inv, b.w);
    reinterpret_cast<float4*>(out)[node * 32 + lane] = o;
}

// ---------------- launch ----------------
extern "C" void kernel_launch(void* const* d_in, const int* in_sizes, int n_in,
                              void* d_out, int out_size)
{
    const float* x_drug  = (const float*)d_in[0];
    const float* x_prot  = (const float*)d_in[1];
    const int*   src_dp  = (const int*)d_in[2];
    const int*   dst_dp  = (const int*)d_in[3];
    const int*   src_pd  = (const int*)d_in[4];
    const int*   dst_pd  = (const int*)d_in[5];
    const float* W_in_d  = (const float*)d_in[6];
    const float* b_in_d  = (const float*)d_in[7];
    const float* W_in_p  = (const float*)d_in[8];
    const float* b_in_p  = (const float*)d_in[9];
    const float* W_dp    = (const float*)d_in[10];
    const float* al_dp   = (const float*)d_in[11];
    const float* ar_dp   = (const float*)d_in[12];
    const float* bias_dp = (const float*)d_in[13];
    const float* W_pd    = (const float*)d_in[14];
    const float* al_pd   = (const float*)d_in[15];
    const float* ar_pd   = (const float*)d_in[16];
    const float* bias_pd = (const float*)d_in[17];
    const float* W_out_d = (const float*)d_in[18];
    const float* b_out_d = (const float*)d_in[19];
    const float* W_out_p = (const float*)d_in[20];
    const float* b_out_p = (const float*)d_in[21];
    float* out = (float*)d_out;

    const int n_drug = in_sizes[0] / HID;
    const int n_prot = in_sizes[1] / HID;
    const int E = in_sizes[2];

    float *h_d, *h_p, *fs_d, *fs_p, *agg_d, *agg_p, *el_d, *er_p, *el_p, *er_d, *Ut_dp, *Ut_pd;
    int *deg_p, *deg_d, *indptr_p, *indptr_d, *cursor_p, *cursor_d, *csrc_p, *csrc_d, *part_p, *part_d;
    cudaGetSymbolAddress((void**)&h_d, g_h_d);
    cudaGetSymbolAddress((void**)&h_p, g_h_p);
    cudaGetSymbolAddress((void**)&fs_d, g_fs_d);
    cudaGetSymbolAddress((void**)&fs_p, g_fs_p);
    cudaGetSymbolAddress((void**)&agg_d, g_agg_d);
    cudaGetSymbolAddress((void**)&agg_p, g_agg_p);
    cudaGetSymbolAddress((void**)&el_d, g_el_d);
    cudaGetSymbolAddress((void**)&er_p, g_er_p);
    cudaGetSymbolAddress((void**)&el_p, g_el_p);
    cudaGetSymbolAddress((void**)&er_d, g_er_d);
    cudaGetSymbolAddress((void**)&Ut_dp, g_Ut_dp);
    cudaGetSymbolAddress((void**)&Ut_pd, g_Ut_pd);
    cudaGetSymbolAddress((void**)&deg_p, g_deg_p);
    cudaGetSymbolAddress((void**)&deg_d, g_deg_d);
    cudaGetSymbolAddress((void**)&indptr_p, g_indptr_p);
    cudaGetSymbolAddress((void**)&indptr_d, g_indptr_d);
    cudaGetSymbolAddress((void**)&cursor_p, g_cursor_p);
    cudaGetSymbolAddress((void**)&cursor_d, g_cursor_d);
    cudaGetSymbolAddress((void**)&csrc_p, g_csrc_p);
    cudaGetSymbolAddress((void**)&csrc_d, g_csrc_d);
    cudaGetSymbolAddress((void**)&part_p, g_part_p);
    cudaGetSymbolAddress((void**)&part_d, g_part_d);

    const int SMEM = (16384 + 8192) * (int)sizeof(float);  // 96 KB
    cudaFuncSetAttribute(gemm128<true,  true,  false>, cudaFuncAttributeMaxDynamicSharedMemorySize, SMEM);
    cudaFuncSetAttribute(gemm128<false, false, true >, cudaFuncAttributeMaxDynamicSharedMemorySize, SMEM);
    cudaFuncSetAttribute(gemm128<false, true,  false>, cudaFuncAttributeMaxDynamicSharedMemorySize, SMEM);

    const int gd = (n_drug + 63) / 64;
    const int gp = (n_prot + 63) / 64;
    const int ge = (E + 255) / 256;
    const int nb_p = (n_prot + 1023) / 1024;
    const int nb_d = (n_drug + 1023) / 1024;

    // CSR build
    cudaMemsetAsync(deg_p, 0, n_prot * sizeof(int));
    cudaMemsetAsync(deg_d, 0, n_drug * sizeof(int));
    count_kernel<<<ge, 256>>>(dst_dp, deg_p, E);
    count_kernel<<<ge, 256>>>(dst_pd, deg_d, E);
    scan_partA<<<nb_p, 1024>>>(deg_p, part_p, n_prot);
    scan_partA<<<nb_d, 1024>>>(deg_d, part_d, n_drug);
    scan_partB<<<1, 1024>>>(part_p, indptr_p, nb_p, n_prot);
    scan_partB<<<1, 1024>>>(part_d, indptr_d, nb_d, n_drug);
    scan_partC<<<nb_p, 1024>>>(deg_p, part_p, indptr_p, cursor_p, n_prot);
    scan_partC<<<nb_d, 1024>>>(deg_d, part_d, indptr_d, cursor_d, n_drug);
    scatter_kernel<<<ge, 256>>>(src_dp, dst_dp, cursor_p, csrc_p, E);
    scatter_kernel<<<ge, 256>>>(src_pd, dst_pd, cursor_d, csrc_d, E);

    // fold attn-right vectors into W (tiny)
    fold_attn_kernel<<<1, 128>>>(W_dp, ar_dp, Ut_dp);
    fold_attn_kernel<<<1, 128>>>(W_pd, ar_pd, Ut_pd);

    // input projections (+relu)
    gemm128<true, true, false><<<gd, 256, SMEM>>>(x_drug, W_in_d, b_in_d, h_d, nullptr, nullptr, n_drug);
    gemm128<true, true, false><<<gp, 256, SMEM>>>(x_prot, W_in_p, b_in_p, h_p, nullptr, nullptr, n_prot);

    // GAT projections: fs (+el fused); er via folded U (no full GEMM)
    gemm128<false, false, true><<<gd, 256, SMEM>>>(h_d, W_dp, nullptr, fs_d, al_dp, el_d, n_drug);
    gemm128<false, false, true><<<gp, 256, SMEM>>>(h_p, W_pd, nullptr, fs_p, al_pd, el_p, n_prot);
    er_kernel<<<(n_prot * 32 + 255) / 256, 256>>>(h_p, Ut_dp, er_p, n_prot);
    er_kernel<<<(n_drug * 32 + 255) / 256, 256>>>(h_d, Ut_pd, er_d, n_drug);

    // edge softmax + aggregation (one warp per dst node)
    aggregate_kernel<<<(n_prot * 32 + 255) / 256, 256>>>(indptr_p, csrc_p, el_d, er_p, fs_d, bias_dp, agg_p, n_prot);
    aggregate_kernel<<<(n_drug * 32 + 255) / 256, 256>>>(indptr_d, csrc_d, el_p, er_d, fs_p, bias_pd, agg_d, n_drug);

    // output projections -> d_out (out_drug first, then out_prot)
    gemm128<false, true, false><<<gd, 256, SMEM>>>(agg_d, W_out_d, b_out_d, out, nullptr, nullptr, n_drug);
    gemm128<false, true, false><<<gp, 256, SMEM>>>(agg_p, W_out_p, b_out_p, out + (size_t)n_drug * HID, nullptr, nullptr, n_prot);
}